// round 7
// baseline (speedup 1.0000x reference)
#include <cuda_runtime.h>
#include <cuda_bf16.h>
#include <cstdint>

// AttentionLayer: out[b,u] = sum_t softmax_t(tanh(x[b,t,:]·W + b[t])) * x[b,t,u]
// B=256, T=2048, U=512, fp32. Single fused HBM pass (tanh in (-1,1) => exp safe
// without max-subtraction).
// R6 (= R5 + missing <cstdint>): cp.async (LDGSTS) 3-stage per-warp smem
// pipeline. No destination registers => 2-3 rows of DRAM traffic in flight per
// warp at ~46 regs (no spill), decoupling DRAM demand from the
// dot->shfl->tanh->exp chain. Per-thread cp.async groups: each lane reads only
// the smem slices it issued, so no mbarrier / no barrier in the mainloop.

#define T_DIM  2048
#define U_DIM  512
#define NWARP  16
#define TPW    (T_DIM / NWARP)   // 128 rows per warp
#define STAGES 3
#define SMEM_BYTES (NWARP * STAGES * U_DIM * 4)   // 96 KB dynamic

__device__ __forceinline__ void cp16(unsigned dst, const void* src) {
    asm volatile("cp.async.cg.shared.global [%0], [%1], 16;\n"
                 :: "r"(dst), "l"(src));
}

__global__ __launch_bounds__(512, 2)
void attn_pool_kernel(const float* __restrict__ x,
                      const float* __restrict__ W,
                      const float* __restrict__ bvec,
                      float* __restrict__ out)
{
    extern __shared__ float sbuf[];          // NWARP*STAGES*512 floats
    __shared__ float ssum[NWARP];

    const int batch = blockIdx.x;
    const int tid   = threadIdx.x;
    const int warp  = tid >> 5;
    const int lane  = tid & 31;

    // Per-lane W slice (u = c*128 + lane*4 + {0..3})
    float4 wv[4];
#pragma unroll
    for (int c = 0; c < 4; c++)
        wv[c] = reinterpret_cast<const float4*>(W)[c * 32 + lane];

    float4 acc[4];
#pragma unroll
    for (int c = 0; c < 4; c++)
        acc[c] = make_float4(0.f, 0.f, 0.f, 0.f);
    float s = 0.f;

    const char* xb = (const char*)x + (size_t)batch * T_DIM * U_DIM * 4;
    const int t0 = warp * TPW;               // contiguous row slab per warp

    float* wstage = sbuf + warp * (STAGES * U_DIM);
    const unsigned sb   = (unsigned)__cvta_generic_to_shared(wstage);
    const unsigned loff = lane * 16;

    // Prologue: rows t0..t0+2 into stages 0..2, one commit group per row.
#pragma unroll
    for (int k = 0; k < STAGES; k++) {
        const char* g = xb + (size_t)(t0 + k) * 2048;
#pragma unroll
        for (int c = 0; c < 4; c++)
            cp16(sb + k * 2048 + c * 512 + loff, g + c * 512 + loff);
        asm volatile("cp.async.commit_group;\n");
    }

    int st = 0;                              // rotating stage index
    for (int i = 0; i < TPW; i++) {
        // Row i's group complete when <= STAGES-1 groups remain pending.
        asm volatile("cp.async.wait_group %0;\n" :: "n"(STAGES - 1));

        const float4* rbuf =
            reinterpret_cast<const float4*>(wstage + st * U_DIM);

        // Dot pass (LDS, conflict-free: lane-striped float4)
        float p = 0.f;
#pragma unroll
        for (int c = 0; c < 4; c++) {
            const float4 v = rbuf[c * 32 + lane];
            p += v.x * wv[c].x + v.y * wv[c].y
               + v.z * wv[c].z + v.w * wv[c].w;
        }
#pragma unroll
        for (int o = 16; o > 0; o >>= 1)
            p += __shfl_xor_sync(0xffffffffu, p, o);

        const float e = tanhf(p + __ldg(&bvec[t0 + i]));
        const float w = __expf(e);           // safe: e in (-1,1)
        s += w;

        // Accumulate pass (second LDS sweep of the same stage)
#pragma unroll
        for (int c = 0; c < 4; c++) {
            const float4 v = rbuf[c * 32 + lane];
            acc[c].x += w * v.x;
            acc[c].y += w * v.y;
            acc[c].z += w * v.z;
            acc[c].w += w * v.w;
        }

        // Refill this stage with row i+STAGES (if any); always commit a group
        // (possibly empty) so group counting stays aligned with iterations.
        if (i + STAGES < TPW) {
            const char* g = xb + (size_t)(t0 + i + STAGES) * 2048;
#pragma unroll
            for (int c = 0; c < 4; c++)
                cp16(sb + st * 2048 + c * 512 + loff, g + c * 512 + loff);
        }
        asm volatile("cp.async.commit_group;\n");

        st = (st == STAGES - 1) ? 0 : st + 1;
    }
    asm volatile("cp.async.wait_group 0;\n");

    // Cross-warp reduction: reuse the staging buffer (all copies drained).
    __syncthreads();
#pragma unroll
    for (int c = 0; c < 4; c++)
        reinterpret_cast<float4*>(sbuf + warp * U_DIM)[c * 32 + lane] = acc[c];
    if (lane == 0) ssum[warp] = s;
    __syncthreads();

    float stot = 0.f;
#pragma unroll
    for (int w2 = 0; w2 < NWARP; w2++) stot += ssum[w2];
    const float inv = 1.0f / stot;

    float v = 0.f;
#pragma unroll
    for (int w2 = 0; w2 < NWARP; w2++)
        v += sbuf[w2 * U_DIM + tid];         // conflict-free: consecutive tids

    out[(size_t)batch * U_DIM + tid] = v * inv;
}

extern "C" void kernel_launch(void* const* d_in, const int* in_sizes, int n_in,
                              void* d_out, int out_size)
{
    const float* x  = (const float*)d_in[0];   // (256, 2048, 512) f32
    const float* W  = (const float*)d_in[1];   // (512, 1) f32
    const float* bv = (const float*)d_in[2];   // (2048, 1) f32
    float* out = (float*)d_out;                // (256, 512) f32

    cudaFuncSetAttribute(attn_pool_kernel,
                         cudaFuncAttributeMaxDynamicSharedMemorySize,
                         SMEM_BYTES);
    attn_pool_kernel<<<256, 512, SMEM_BYTES>>>(x, W, bv, out);
}

// round 8
// speedup vs baseline: 1.0214x; 1.0214x over previous
#include <cuda_runtime.h>
#include <cuda_bf16.h>
#include <cstdint>

// AttentionLayer: out[b,u] = sum_t softmax_t(tanh(x[b,t,:]·W + b[t])) * x[b,t,u]
// B=256, T=2048, U=512, fp32. Single fused HBM pass (tanh in (-1,1) => exp
// safe without max-subtraction).
// R7: fix CTA load imbalance. 512 uniform work units (batch x half-T) on
// 256-thread CTAs at occupancy 4 -> all CTAs co-resident (no wave split),
// SM skew 2:1 -> 4:3, half-size tail. Inner loop identical to R4 (register
// row buffer + zero-reg L2 prefetch). Partials combined by a tiny second
// kernel (scratch in __device__ globals; graph-capturable, no allocation).

#define B_DIM  256
#define T_DIM  2048
#define U_DIM  512
#define NSPLIT 2                       // T split factor
#define NUNIT  (B_DIM * NSPLIT)        // 512 work units
#define NWARP  8                       // warps per CTA (256 threads)
#define ROWS_PER_UNIT (T_DIM / NSPLIT) // 1024
#define TPW    (ROWS_PER_UNIT / NWARP) // 128 rows per warp

__device__ float g_acc[NUNIT][U_DIM];  // 1 MB partial weighted sums
__device__ float g_s[NUNIT];           // partial softmax denominators

__device__ __forceinline__ void prefetch_l2(const void* p) {
    asm volatile("prefetch.global.L2 [%0];" :: "l"(p));
}

__global__ __launch_bounds__(256, 4)
void attn_partial_kernel(const float* __restrict__ x,
                         const float* __restrict__ W,
                         const float* __restrict__ bvec)
{
    __shared__ float sacc[NWARP * U_DIM];   // 16 KB per CTA
    __shared__ float ssum[NWARP];

    const int unit  = blockIdx.x;           // 0..511
    const int batch = unit >> 1;
    const int half  = unit & 1;
    const int tid   = threadIdx.x;
    const int warp  = tid >> 5;
    const int lane  = tid & 31;

    // Per-lane W slice: lane holds u = c*128 + lane*4 + {0..3}
    float4 wv[4];
#pragma unroll
    for (int c = 0; c < 4; c++)
        wv[c] = reinterpret_cast<const float4*>(W)[c * 32 + lane];

    float4 acc[4];
#pragma unroll
    for (int c = 0; c < 4; c++)
        acc[c] = make_float4(0.f, 0.f, 0.f, 0.f);
    float s = 0.f;

    const float4* xb = reinterpret_cast<const float4*>(
        x + (size_t)batch * T_DIM * U_DIM);

    // Contiguous 128-row slab per warp inside this unit's half of T.
    const int t0 = half * ROWS_PER_UNIT + warp * TPW;

    for (int i = 0; i < TPW; i++) {
        const int t = t0 + i;
        const float4* rowp = xb + (size_t)t * 128 + lane;

        // Full 512-float row across the warp: 4x float4 per lane, coalesced.
        float4 xv[4];
#pragma unroll
        for (int c = 0; c < 4; c++)
            xv[c] = rowp[c * 32];

        // Zero-register L2 prefetch of the next row ([R+imm] addressing).
        if (i + 1 < TPW) {
#pragma unroll
            for (int c = 0; c < 4; c++)
                prefetch_l2(rowp + c * 32 + 128);
        }

        // Dot with W
        float p = 0.f;
#pragma unroll
        for (int c = 0; c < 4; c++)
            p += xv[c].x * wv[c].x + xv[c].y * wv[c].y
               + xv[c].z * wv[c].z + xv[c].w * wv[c].w;

        // Warp butterfly reduction
#pragma unroll
        for (int o = 16; o > 0; o >>= 1)
            p += __shfl_xor_sync(0xffffffffu, p, o);

        const float e = tanhf(p + bvec[t]);
        const float w = __expf(e);          // safe: e in (-1,1)
        s += w;

#pragma unroll
        for (int c = 0; c < 4; c++) {
            acc[c].x += w * xv[c].x;
            acc[c].y += w * xv[c].y;
            acc[c].z += w * xv[c].z;
            acc[c].w += w * xv[c].w;
        }
    }

    // Per-warp partials -> shared
#pragma unroll
    for (int c = 0; c < 4; c++)
        reinterpret_cast<float4*>(sacc + warp * U_DIM)[c * 32 + lane] = acc[c];
    if (lane == 0) ssum[warp] = s;
    __syncthreads();

    // Cross-warp reduce: each thread owns 2 output elements (u = tid, tid+256)
    if (tid == 0) {
        float stot = 0.f;
#pragma unroll
        for (int w2 = 0; w2 < NWARP; w2++) stot += ssum[w2];
        g_s[unit] = stot;
    }
#pragma unroll
    for (int k = 0; k < 2; k++) {
        const int u = tid + k * 256;
        float v = 0.f;
#pragma unroll
        for (int w2 = 0; w2 < NWARP; w2++)
            v += sacc[w2 * U_DIM + u];
        g_acc[unit][u] = v;
    }
}

// Combine the NSPLIT partials per batch and normalize.
__global__ __launch_bounds__(512, 4)
void attn_combine_kernel(float* __restrict__ out)
{
    const int batch = blockIdx.x;
    const int u     = threadIdx.x;
    const float stot = g_s[batch * 2] + g_s[batch * 2 + 1];
    const float v    = g_acc[batch * 2][u] + g_acc[batch * 2 + 1][u];
    out[(size_t)batch * U_DIM + u] = v / stot;
}

extern "C" void kernel_launch(void* const* d_in, const int* in_sizes, int n_in,
                              void* d_out, int out_size)
{
    const float* x  = (const float*)d_in[0];   // (256, 2048, 512) f32
    const float* W  = (const float*)d_in[1];   // (512, 1) f32
    const float* bv = (const float*)d_in[2];   // (2048, 1) f32
    float* out = (float*)d_out;                // (256, 512) f32

    attn_partial_kernel<<<NUNIT, 256>>>(x, W, bv);
    attn_combine_kernel<<<B_DIM, U_DIM>>>(out);
}

// round 9
// speedup vs baseline: 1.0403x; 1.0184x over previous
#include <cuda_runtime.h>
#include <cuda_bf16.h>
#include <cstdint>

// AttentionLayer: out[b,u] = sum_t softmax_t(tanh(x[b,t,:]·W + b[t])) * x[b,t,u]
// B=256, T=2048, U=512, fp32. Single fused HBM pass (tanh in (-1,1) => exp
// safe without max-subtraction).
// R8: R7's balanced 512-unit split (batch x half-T, 256-thread CTAs, occ 4,
// all CTAs co-resident) + combine folded into the main kernel via the
// threadfence-reduction pattern: the second-finishing CTA of each batch pair
// does the 512-elem combine+normalize inline. Deletes R7's 4.2us second
// launch; combine overlaps with other CTAs' streaming.

#define B_DIM  256
#define T_DIM  2048
#define U_DIM  512
#define NSPLIT 2                       // T split factor
#define NUNIT  (B_DIM * NSPLIT)        // 512 work units
#define NWARP  8                       // warps per CTA (256 threads)
#define ROWS_PER_UNIT (T_DIM / NSPLIT) // 1024
#define TPW    (ROWS_PER_UNIT / NWARP) // 128 rows per warp

__device__ float        g_acc[NUNIT][U_DIM]; // 1 MB partial weighted sums
__device__ float        g_s[NUNIT];          // partial denominators
__device__ unsigned int g_ticket[B_DIM];     // zero-initialized; combiner resets

__device__ __forceinline__ void prefetch_l2(const void* p) {
    asm volatile("prefetch.global.L2 [%0];" :: "l"(p));
}

__global__ __launch_bounds__(256, 4)
void attn_pool_kernel(const float* __restrict__ x,
                      const float* __restrict__ W,
                      const float* __restrict__ bvec,
                      float* __restrict__ out)
{
    __shared__ float sacc[NWARP * U_DIM];   // 16 KB per CTA
    __shared__ float ssum[NWARP];
    __shared__ int   s_last;

    const int unit  = blockIdx.x;           // 0..511
    const int batch = unit >> 1;
    const int half  = unit & 1;
    const int tid   = threadIdx.x;
    const int warp  = tid >> 5;
    const int lane  = tid & 31;

    // Per-lane W slice: lane holds u = c*128 + lane*4 + {0..3}
    float4 wv[4];
#pragma unroll
    for (int c = 0; c < 4; c++)
        wv[c] = reinterpret_cast<const float4*>(W)[c * 32 + lane];

    float4 acc[4];
#pragma unroll
    for (int c = 0; c < 4; c++)
        acc[c] = make_float4(0.f, 0.f, 0.f, 0.f);
    float s = 0.f;

    const float4* xb = reinterpret_cast<const float4*>(
        x + (size_t)batch * T_DIM * U_DIM);

    // Contiguous 128-row slab per warp inside this unit's half of T.
    const int t0 = half * ROWS_PER_UNIT + warp * TPW;

    for (int i = 0; i < TPW; i++) {
        const int t = t0 + i;
        const float4* rowp = xb + (size_t)t * 128 + lane;

        // Full 512-float row across the warp: 4x float4 per lane, coalesced.
        float4 xv[4];
#pragma unroll
        for (int c = 0; c < 4; c++)
            xv[c] = rowp[c * 32];

        // Zero-register L2 prefetch of the next row ([R+imm] addressing).
        if (i + 1 < TPW) {
#pragma unroll
            for (int c = 0; c < 4; c++)
                prefetch_l2(rowp + c * 32 + 128);
        }

        // Dot with W
        float p = 0.f;
#pragma unroll
        for (int c = 0; c < 4; c++)
            p += xv[c].x * wv[c].x + xv[c].y * wv[c].y
               + xv[c].z * wv[c].z + xv[c].w * wv[c].w;

        // Warp butterfly reduction
#pragma unroll
        for (int o = 16; o > 0; o >>= 1)
            p += __shfl_xor_sync(0xffffffffu, p, o);

        const float e = tanhf(p + bvec[t]);
        const float w = __expf(e);          // safe: e in (-1,1)
        s += w;

#pragma unroll
        for (int c = 0; c < 4; c++) {
            acc[c].x += w * xv[c].x;
            acc[c].y += w * xv[c].y;
            acc[c].z += w * xv[c].z;
            acc[c].w += w * xv[c].w;
        }
    }

    // Per-warp partials -> shared
#pragma unroll
    for (int c = 0; c < 4; c++)
        reinterpret_cast<float4*>(sacc + warp * U_DIM)[c * 32 + lane] = acc[c];
    if (lane == 0) ssum[warp] = s;
    __syncthreads();

    // Cross-warp reduce -> this unit's global partial (u = tid, tid+256)
    if (tid == 0) {
        float stot = 0.f;
#pragma unroll
        for (int w2 = 0; w2 < NWARP; w2++) stot += ssum[w2];
        g_s[unit] = stot;
    }
#pragma unroll
    for (int k = 0; k < 2; k++) {
        const int u = tid + k * 256;
        float v = 0.f;
#pragma unroll
        for (int w2 = 0; w2 < NWARP; w2++)
            v += sacc[w2 * U_DIM + u];
        g_acc[unit][u] = v;
    }

    // Threadfence-reduction handoff: second CTA of the pair combines.
    __threadfence();
    __syncthreads();
    if (tid == 0)
        s_last = (atomicAdd(&g_ticket[batch], 1u) == 1u);
    __syncthreads();

    if (s_last) {
        __threadfence();                    // acquire partner's partials
        const float stot = g_s[batch * 2] + g_s[batch * 2 + 1];
        const float inv  = 1.0f / stot;
#pragma unroll
        for (int k = 0; k < 2; k++) {
            const int u = tid + k * 256;    // deterministic: fixed add order
            out[(size_t)batch * U_DIM + u] =
                (g_acc[batch * 2][u] + g_acc[batch * 2 + 1][u]) * inv;
        }
        if (tid == 0) g_ticket[batch] = 0;  // reset for next graph replay
    }
}

extern "C" void kernel_launch(void* const* d_in, const int* in_sizes, int n_in,
                              void* d_out, int out_size)
{
    const float* x  = (const float*)d_in[0];   // (256, 2048, 512) f32
    const float* W  = (const float*)d_in[1];   // (512, 1) f32
    const float* bv = (const float*)d_in[2];   // (2048, 1) f32
    float* out = (float*)d_out;                // (256, 512) f32

    attn_pool_kernel<<<NUNIT, 256>>>(x, W, bv, out);
}